// round 2
// baseline (speedup 1.0000x reference)
#include <cuda_runtime.h>
#include <cuda_bf16.h>
#include <math.h>

#define BB 32
#define SS 512
#define HH 768
#define KK 4
#define HOPS 3
#define H2 1536
#define H3 2304

// ---------------- scratch (device globals; no allocation) ----------------
__device__ float g_Wc[(size_t)KK*HH*HH];          // combined pw@Ws  (9.4MB)
__device__ float g_bc[KK*HH];                      // combined bias
__device__ float g_Whs[(size_t)KK*BB*SS*HH];       // [K,B,S,H] 201MB
__device__ float g_Wht[KK*BB*HH];                  // [K,B,H]
__device__ float g_scores[KK*BB*SS];               // scores / alpha in-place
__device__ float g_qbuf[BB*HH];
__device__ float g_hbuf[BB*HH];
__device__ float g_GX[BB*H3];
__device__ float g_GH[BB*H3];
__device__ int   g_idx[BB];

// ---------------- prologue: qbuf = question, h = 0 ----------------
__global__ void k_prologue(const float* __restrict__ question) {
    int t = blockIdx.x * 256 + threadIdx.x;
    if (t < BB*HH) { g_qbuf[t] = question[t]; g_hbuf[t] = 0.f; }
}

// ---------------- combined bias: bc[k][j] = pw_b[k] @ Ws_W[k] + Ws_b[k] ----------------
__global__ void k_bc(const float* __restrict__ pw_b, const float* __restrict__ Ws_W,
                     const float* __restrict__ Ws_b) {
    int k = blockIdx.x;
    int j = blockIdx.y * 256 + threadIdx.x;
    float acc = Ws_b[k*HH + j];
    const float* W = Ws_W + (size_t)k*HH*HH;
    const float* b = pw_b + k*HH;
    #pragma unroll 4
    for (int m = 0; m < HH; m++) acc = fmaf(b[m], W[(size_t)m*HH + j], acc);
    g_bc[k*HH + j] = acc;
}

// ---------------- generic batched SGEMM: C = A@B (+bias), all row-major ----------------
// BM=128, BN=128, BK=8, 256 threads, 8x8 per-thread. M%128==0, N%128==0, Kd%8==0.
__global__ __launch_bounds__(256, 2)
void k_sgemm(const float* __restrict__ A, size_t strideA,
             const float* __restrict__ Bm, size_t strideB,
             float* __restrict__ C, size_t strideC,
             const float* __restrict__ bias, size_t strideBias,
             int M, int N, int Kd)
{
    const int batch = blockIdx.z;
    const float* Ab = A + (size_t)batch * strideA;
    const float* Bb = Bm + (size_t)batch * strideB;
    float* Cb = C + (size_t)batch * strideC;

    __shared__ float As[8][128];
    __shared__ float Bs[8][128];

    const int tid = threadIdx.x;
    const int tx = tid & 15, ty = tid >> 4;
    const int m0 = blockIdx.y * 128;
    const int n0 = blockIdx.x * 128;

    const int a_row = tid >> 1;
    const int a_col = (tid & 1) * 4;
    const int b_kk  = tid >> 5;
    const int b_col = (tid & 31) * 4;

    float acc[8][8];
    #pragma unroll
    for (int i = 0; i < 8; i++)
        #pragma unroll
        for (int j = 0; j < 8; j++) acc[i][j] = 0.f;

    for (int k0 = 0; k0 < Kd; k0 += 8) {
        float4 a4 = *(const float4*)(Ab + (size_t)(m0 + a_row)*Kd + k0 + a_col);
        As[a_col+0][a_row] = a4.x;
        As[a_col+1][a_row] = a4.y;
        As[a_col+2][a_row] = a4.z;
        As[a_col+3][a_row] = a4.w;
        float4 b4 = *(const float4*)(Bb + (size_t)(k0 + b_kk)*N + n0 + b_col);
        *(float4*)&Bs[b_kk][b_col] = b4;
        __syncthreads();
        #pragma unroll
        for (int kk = 0; kk < 8; kk++) {
            float ra[8], rb[8];
            *(float4*)&ra[0] = *(const float4*)&As[kk][ty*8];
            *(float4*)&ra[4] = *(const float4*)&As[kk][ty*8 + 4];
            *(float4*)&rb[0] = *(const float4*)&Bs[kk][tx*8];
            *(float4*)&rb[4] = *(const float4*)&Bs[kk][tx*8 + 4];
            #pragma unroll
            for (int i = 0; i < 8; i++)
                #pragma unroll
                for (int j = 0; j < 8; j++)
                    acc[i][j] = fmaf(ra[i], rb[j], acc[i][j]);
        }
        __syncthreads();
    }

    float bv[8];
    #pragma unroll
    for (int j = 0; j < 8; j++)
        bv[j] = bias ? bias[(size_t)batch*strideBias + n0 + tx*8 + j] : 0.f;

    #pragma unroll
    for (int i = 0; i < 8; i++) {
        float* cp = Cb + (size_t)(m0 + ty*8 + i)*N + n0 + tx*8;
        float4 o0, o1;
        o0.x = acc[i][0]+bv[0]; o0.y = acc[i][1]+bv[1];
        o0.z = acc[i][2]+bv[2]; o0.w = acc[i][3]+bv[3];
        o1.x = acc[i][4]+bv[4]; o1.y = acc[i][5]+bv[5];
        o1.z = acc[i][6]+bv[6]; o1.w = acc[i][7]+bv[7];
        *(float4*)cp = o0;
        *(float4*)(cp+4) = o1;
    }
}

// ---------------- W_ht = qbuf @ Wt_W[k] + Wt_b[k]  (k-split, atomic) ----------------
__global__ void k_init_wht(const float* __restrict__ Wt_b) {
    int t = blockIdx.x * 256 + threadIdx.x;
    if (t < KK*BB*HH) {
        int k = t / (BB*HH);
        int j = t % HH;
        g_Wht[t] = Wt_b[k*HH + j];
    }
}

__global__ void k_wht(const float* __restrict__ Wt_W) {
    int k  = blockIdx.x;       // K
    int jc = blockIdx.y;       // 6
    int hs = blockIdx.z;       // 6
    int t  = threadIdx.x;      // 128
    int j  = jc*128 + t;
    int h0 = hs*128;
    __shared__ float qs[32][128];
    #pragma unroll 8
    for (int r = 0; r < 32; r++) qs[r][t] = g_qbuf[r*HH + h0 + t];
    __syncthreads();
    float acc[32];
    #pragma unroll
    for (int b = 0; b < 32; b++) acc[b] = 0.f;
    for (int hh = 0; hh < 128; hh++) {
        float w = Wt_W[((size_t)k*HH + h0 + hh)*HH + j];
        #pragma unroll
        for (int b = 0; b < 32; b++) acc[b] = fmaf(qs[b][hh], w, acc[b]);
    }
    #pragma unroll
    for (int b = 0; b < 32; b++) atomicAdd(&g_Wht[(k*BB + b)*HH + j], acc[b]);
}

// ---------------- scores[k,b,s] = We . tanh(W_hs + W_ht) + We_b ----------------
__global__ void k_scores(const float* __restrict__ WeW, const float* __restrict__ Web) {
    int kb = blockIdx.x;            // K*B
    int sc = blockIdx.y;            // 4 chunks of 128 s
    int k = kb / BB;
    __shared__ float sh[2*HH];
    for (int i = threadIdx.x; i < HH; i += 256) {
        sh[i]      = g_Wht[kb*HH + i];
        sh[HH + i] = WeW[k*HH + i];
    }
    __syncthreads();
    int warp = threadIdx.x >> 5, lane = threadIdx.x & 31;
    float web = Web[k];
    for (int s = sc*128 + warp; s < sc*128 + 128; s += 8) {
        const float* row = g_Whs + (((size_t)kb*SS + s))*HH;
        float sum = 0.f;
        #pragma unroll
        for (int i = 0; i < HH/32; i++) {
            int h = lane + i*32;
            float x = row[h] + sh[h];
            // tanh(x) = 1 - 2/(exp(2x)+1), exact identity via fast exp/div
            float e = __expf(2.f * x);
            float t = 1.f - __fdividef(2.f, e + 1.f);
            sum = fmaf(t, sh[HH + h], sum);
        }
        #pragma unroll
        for (int o = 16; o; o >>= 1) sum += __shfl_xor_sync(0xffffffffu, sum, o);
        if (lane == 0) g_scores[kb*SS + s] = sum + web;
    }
}

// ---------------- softmax over S, in place ----------------
__global__ void k_softmax() {
    __shared__ float red[256];
    int row = blockIdx.x;            // K*B
    float* p = g_scores + (size_t)row * SS;
    int t = threadIdx.x;
    float a = p[t], b = p[t + 256];
    red[t] = fmaxf(a, b);
    __syncthreads();
    for (int o = 128; o; o >>= 1) { if (t < o) red[t] = fmaxf(red[t], red[t+o]); __syncthreads(); }
    float m = red[0];
    __syncthreads();
    float e0 = __expf(a - m), e1 = __expf(b - m);
    red[t] = e0 + e1;
    __syncthreads();
    for (int o = 128; o; o >>= 1) { if (t < o) red[t] += red[t+o]; __syncthreads(); }
    float inv = 1.f / red[0];
    p[t] = e0 * inv;
    p[t + 256] = e1 * inv;
}

// ---------------- alpha_linear, prob (hop 0), argmax ----------------
__global__ void k_alpha(const float* __restrict__ hw, const float* __restrict__ hb,
                        float* __restrict__ out_prob, int hop) {
    int b = blockIdx.x;             // 32
    int s = threadIdx.x;            // 512
    float al = hb[0];
    #pragma unroll
    for (int k = 0; k < KK; k++) al = fmaf(g_scores[(k*BB + b)*SS + s], hw[k], al);
    __shared__ float ssq[512];
    __shared__ float sval[512];
    __shared__ int   sidx[512];
    ssq[s] = al * al; sval[s] = al; sidx[s] = s;
    __syncthreads();
    for (int o = 256; o; o >>= 1) {
        if (s < o) {
            ssq[s] += ssq[s + o];
            float v2 = sval[s + o]; int i2 = sidx[s + o];
            if (v2 > sval[s] || (v2 == sval[s] && i2 < sidx[s])) { sval[s] = v2; sidx[s] = i2; }
        }
        __syncthreads();
    }
    if (s == 0) g_idx[b] = sidx[0];
    if (hop == 0) out_prob[b*SS + s] = al / sqrtf(ssq[0]);
}

// ---------------- GRU: G init with biases ----------------
__global__ void k_gru_init(const float* __restrict__ bih, const float* __restrict__ bhh) {
    int t = blockIdx.x * 256 + threadIdx.x;
    if (t < BB*H3) { int j = t % H3; g_GX[t] = bih[j]; g_GH[t] = bhh[j]; }
}

// ---------------- GRU gemm: GX += x@Wih, GH += h@Whh (k-split, atomic) ----------------
// virtual input dim 2304: [0,768)=qbuf, [768,1536)=text[b,idx[b]], [1536,2304)=hbuf
__global__ void k_grugemm(const float* __restrict__ Wih, const float* __restrict__ Whh,
                          const float* __restrict__ text) {
    int jc = blockIdx.x;        // 9 -> j chunk of 256
    int ks = blockIdx.y;        // 9 -> virtual-i chunk of 256
    int bg = blockIdx.z;        // 4 -> 8 batches
    int t = threadIdx.x;        // 256
    int j = jc*256 + t;
    int i0 = ks*256;
    __shared__ float xs[8][256];
    int i = i0 + t;
    #pragma unroll
    for (int r = 0; r < 8; r++) {
        int b = bg*8 + r;
        float v;
        if (i < 768)       v = g_qbuf[b*HH + i];
        else if (i < 1536) v = text[((size_t)b*SS + g_idx[b])*HH + (i - 768)];
        else               v = g_hbuf[b*HH + (i - 1536)];
        xs[r][t] = v;
    }
    __syncthreads();
    const float* W; int wi0; float* G;
    if (i0 < 1536) { W = Wih; wi0 = i0;        G = g_GX; }
    else           { W = Whh; wi0 = i0 - 1536; G = g_GH; }
    float acc[8];
    #pragma unroll
    for (int r = 0; r < 8; r++) acc[r] = 0.f;
    #pragma unroll 4
    for (int kk = 0; kk < 256; kk++) {
        float w = W[(size_t)(wi0 + kk)*H3 + j];
        #pragma unroll
        for (int r = 0; r < 8; r++) acc[r] = fmaf(xs[r][kk], w, acc[r]);
    }
    #pragma unroll
    for (int r = 0; r < 8; r++) atomicAdd(&G[(bg*8 + r)*H3 + j], acc[r]);
}

// ---------------- GRU gates + state update + output ----------------
__global__ void k_grugate(float* __restrict__ out_h, int hop) {
    int t = blockIdx.x * 256 + threadIdx.x;
    if (t >= BB*HH) return;
    int b = t / HH, j = t % HH;
    float gxr = g_GX[b*H3 + j],        ghr = g_GH[b*H3 + j];
    float gxz = g_GX[b*H3 + HH + j],   ghz = g_GH[b*H3 + HH + j];
    float gxn = g_GX[b*H3 + 2*HH + j], ghn = g_GH[b*H3 + 2*HH + j];
    float r = 1.f / (1.f + expf(-(gxr + ghr)));
    float z = 1.f / (1.f + expf(-(gxz + ghz)));
    float n = tanhf(gxn + r * ghn);
    float hprev = g_hbuf[t];
    float hn = (1.f - z) * n + z * hprev;
    g_hbuf[t] = hn;
    g_qbuf[t] = hn;
    out_h[((size_t)b*HOPS + hop)*HH + j] = hn;
}

// ---------------- launch ----------------
extern "C" void kernel_launch(void* const* d_in, const int* in_sizes, int n_in,
                              void* d_out, int out_size) {
    const float* question = (const float*)d_in[0];
    const float* text     = (const float*)d_in[1];
    const float* pw_W     = (const float*)d_in[2];
    const float* pw_b     = (const float*)d_in[3];
    const float* Ws_W     = (const float*)d_in[4];
    const float* Ws_b     = (const float*)d_in[5];
    const float* Wt_W     = (const float*)d_in[6];
    const float* Wt_b     = (const float*)d_in[7];
    const float* We_W     = (const float*)d_in[8];
    const float* We_b     = (const float*)d_in[9];
    const float* headw_W  = (const float*)d_in[10];
    const float* headw_b  = (const float*)d_in[11];
    const float* gru_Wih  = (const float*)d_in[12];
    const float* gru_Whh  = (const float*)d_in[13];
    const float* gru_bih  = (const float*)d_in[14];
    const float* gru_bhh  = (const float*)d_in[15];

    float* out_prob = (float*)d_out;               // [B,S]
    float* out_h    = (float*)d_out + BB*SS;       // [B,HOP,H]

    float *p_Wc, *p_bc, *p_Whs;
    cudaGetSymbolAddress((void**)&p_Wc,  g_Wc);
    cudaGetSymbolAddress((void**)&p_bc,  g_bc);
    cudaGetSymbolAddress((void**)&p_Whs, g_Whs);

    k_prologue<<<(BB*HH + 255)/256, 256>>>(question);
    k_bc<<<dim3(KK, HH/256), 256>>>(pw_b, Ws_W, Ws_b);

    // Wc[k] = pw_W[k] @ Ws_W[k]
    k_sgemm<<<dim3(HH/128, HH/128, KK), 256>>>(
        pw_W, (size_t)HH*HH, Ws_W, (size_t)HH*HH,
        p_Wc, (size_t)HH*HH, nullptr, 0, HH, HH, HH);

    // W_hs[k] = text @ Wc[k] + bc[k]   (M=16384, N=768, K=768, batch 4)
    k_sgemm<<<dim3(HH/128, (BB*SS)/128, KK), 256>>>(
        text, 0, p_Wc, (size_t)HH*HH,
        p_Whs, (size_t)BB*SS*HH, p_bc, HH, BB*SS, HH, HH);

    for (int hop = 0; hop < HOPS; hop++) {
        k_init_wht<<<(KK*BB*HH + 255)/256, 256>>>(Wt_b);
        k_wht<<<dim3(KK, HH/128, HH/128), 128>>>(Wt_W);
        k_scores<<<dim3(KK*BB, SS/128), 256>>>(We_W, We_b);
        k_softmax<<<KK*BB, 256>>>();
        k_alpha<<<BB, 512>>>(headw_W, headw_b, out_prob, hop);
        k_gru_init<<<(BB*H3 + 255)/256, 256>>>(gru_bih, gru_bhh);
        k_grugemm<<<dim3(H3/256, H3/256, BB/8), 256>>>(gru_Wih, gru_Whh, text);
        k_grugate<<<(BB*HH + 255)/256, 256>>>(out_h, hop);
    }
}

// round 4
// speedup vs baseline: 1.6541x; 1.6541x over previous
#include <cuda_runtime.h>
#include <cuda_bf16.h>
#include <math.h>
#include <stdint.h>

#define BB 32
#define SS 512
#define HH 768
#define KK 4
#define HOPS 3
#define H2 1536
#define H3 2304
#define MROWS (BB*SS)

// ---------------- scratch (device globals; no allocation) ----------------
__device__ float g_Wc[(size_t)KK*HH*HH];
__device__ float g_bc[KK*HH];
__device__ float g_Whs[(size_t)KK*MROWS*HH];       // [K,B,S,H] 201MB
__device__ float g_Wht[KK*BB*HH];
__device__ float g_scores[KK*BB*SS];
__device__ float g_qbuf[BB*HH];
__device__ float g_hbuf[BB*HH];
__device__ float g_GX[BB*H3];
__device__ float g_GH[BB*H3];
__device__ int   g_idx[BB];
// split-bf16 operands
__device__ __nv_bfloat16 g_tAhi[(size_t)MROWS*HH];
__device__ __nv_bfloat16 g_tAlo[(size_t)MROWS*HH];
__device__ __nv_bfloat16 g_pwhi[(size_t)KK*HH*HH];
__device__ __nv_bfloat16 g_pwlo[(size_t)KK*HH*HH];
__device__ __nv_bfloat16 g_WsThi[(size_t)KK*HH*HH];
__device__ __nv_bfloat16 g_WsTlo[(size_t)KK*HH*HH];
__device__ __nv_bfloat16 g_WcThi[(size_t)KK*HH*HH];
__device__ __nv_bfloat16 g_WcTlo[(size_t)KK*HH*HH];

// ---------------- helpers ----------------
__device__ __forceinline__ uint32_t smem_u32(const void* p) {
    uint32_t a;
    asm("{ .reg .u64 t; cvta.to.shared.u64 t, %1; cvt.u32.u64 %0, t; }" : "=r"(a) : "l"(p));
    return a;
}
__device__ __forceinline__ void mma16816(float* d, const uint32_t* a, const uint32_t* b) {
    asm volatile("mma.sync.aligned.m16n8k16.row.col.f32.bf16.bf16.f32 "
        "{%0,%1,%2,%3},{%4,%5,%6,%7},{%8,%9},{%0,%1,%2,%3};"
        : "+f"(d[0]), "+f"(d[1]), "+f"(d[2]), "+f"(d[3])
        : "r"(a[0]), "r"(a[1]), "r"(a[2]), "r"(a[3]), "r"(b[0]), "r"(b[1]));
}
__device__ __forceinline__ void cp16(uint32_t dst, const void* src) {
    asm volatile("cp.async.cg.shared.global [%0], [%1], 16;" :: "r"(dst), "l"(src));
}
#define CP_COMMIT() asm volatile("cp.async.commit_group;" ::: "memory")
#define CP_WAIT0()  asm volatile("cp.async.wait_group 0;" ::: "memory")

// ---------------- split helpers ----------------
__device__ __forceinline__ void split2(float x, __nv_bfloat16& h, __nv_bfloat16& l) {
    __nv_bfloat16 hb = __float2bfloat16(x);
    h = hb;
    l = __float2bfloat16(x - __bfloat162float(hb));
}

__global__ void k_split(const float* __restrict__ src, __nv_bfloat16* __restrict__ dhi,
                        __nv_bfloat16* __restrict__ dlo, int n) {
    int i = blockIdx.x * 256 + threadIdx.x;
    if (i < n) split2(src[i], dhi[i], dlo[i]);
}

// transpose + split: src [R=768, C=768] per batch -> dst [C, R]
__global__ void k_splitT(const float* __restrict__ src, __nv_bfloat16* __restrict__ dhi,
                         __nv_bfloat16* __restrict__ dlo) {
    __shared__ float t[32][33];
    int b = blockIdx.z;
    const float* S = src + (size_t)b * HH * HH;
    __nv_bfloat16* Dh = dhi + (size_t)b * HH * HH;
    __nv_bfloat16* Dl = dlo + (size_t)b * HH * HH;
    int r0 = blockIdx.y * 32, c0 = blockIdx.x * 32;
    for (int rr = threadIdx.y; rr < 32; rr += 8)
        t[rr][threadIdx.x] = S[(size_t)(r0 + rr) * HH + c0 + threadIdx.x];
    __syncthreads();
    for (int rr = threadIdx.y; rr < 32; rr += 8) {
        float v = t[threadIdx.x][rr];
        size_t o = (size_t)(c0 + rr) * HH + r0 + threadIdx.x;
        split2(v, Dh[o], Dl[o]);
    }
}

// ---------------- HMMA split-bf16 GEMM (mma.sync m16n8k16) ----------------
// C[m,n] = sum_k A[m,k]*B[n,k] (+bias[n]); A [M,Kd] rm, B [N,Kd] rm, C ld=HH.
// BM=128, BN=128, BK=32; 8 warps 2x4; warp tile 64x32. 3 products hi*hi+hi*lo+lo*hi.
#define BKH 32
#define ROWP 40                       // padded row length (bf16) -> conflict-free
#define ARR_BYTES (128*ROWP*2)        // 10240
#define STAGE_SZ (4*ARR_BYTES)        // 40960
#define HMMA_SMEM (2*STAGE_SZ)        // 81920

__global__ __launch_bounds__(256, 1)
void k_hmma(const __nv_bfloat16* __restrict__ Ahi, const __nv_bfloat16* __restrict__ Alo,
            size_t strideA,
            const __nv_bfloat16* __restrict__ Bhi, const __nv_bfloat16* __restrict__ Blo,
            size_t strideB,
            float* __restrict__ C, size_t strideC,
            const float* __restrict__ bias, int Kd)
{
    extern __shared__ char smem[];
    const uint32_t sb = smem_u32(smem);
    const int tid = threadIdx.x;
    const int lane = tid & 31;
    const int warp = tid >> 5;
    const int wm = warp >> 2, wn = warp & 3;
    const int bat = blockIdx.z;
    const int m0 = blockIdx.y * 128;
    const int n0 = blockIdx.x * 128;

    const __nv_bfloat16* srcs[4] = {
        Ahi + (size_t)bat * strideA + (size_t)m0 * Kd,
        Alo + (size_t)bat * strideA + (size_t)m0 * Kd,
        Bhi + (size_t)bat * strideB + (size_t)n0 * Kd,
        Blo + (size_t)bat * strideB + (size_t)n0 * Kd };

    // per-thread 8 cp.async chunks (2048 chunks of 16B per stage)
    const __nv_bfloat16* gsrc[8];
    uint32_t dsto[8];
    #pragma unroll
    for (int i = 0; i < 8; i++) {
        int id = i * 256 + tid;
        int arr = id >> 9, rem = id & 511, row = rem >> 2, cj = rem & 3;
        gsrc[i] = srcs[arr] + (size_t)row * Kd + cj * 8;
        dsto[i] = (uint32_t)arr * ARR_BYTES + (uint32_t)row * (ROWP*2) + (uint32_t)cj * 16;
    }

    float acc[4][4][4];
    #pragma unroll
    for (int mi = 0; mi < 4; mi++)
        #pragma unroll
        for (int ni = 0; ni < 4; ni++)
            #pragma unroll
            for (int j = 0; j < 4; j++) acc[mi][ni][j] = 0.f;

    const int nIt = Kd / BKH;

#define LOAD_STAGE(it) do {                                       \
        uint32_t s_ = sb + ((it) & 1) * STAGE_SZ;                 \
        int ko_ = (it) * BKH;                                     \
        _Pragma("unroll")                                         \
        for (int i_ = 0; i_ < 8; i_++)                            \
            cp16(s_ + dsto[i_], gsrc[i_] + ko_);                  \
        CP_COMMIT();                                              \
    } while (0)

    LOAD_STAGE(0);

    const int r  = lane >> 2;
    const int c2 = (lane & 3) * 2;

    for (int it = 0; it < nIt; ++it) {
        CP_WAIT0();
        __syncthreads();
        if (it + 1 < nIt) LOAD_STAGE(it + 1);

        const char* st = smem + (it & 1) * STAGE_SZ;
        const char* pAh = st;
        const char* pAl = st + ARR_BYTES;
        const char* pBh = st + 2 * ARR_BYTES;
        const char* pBl = st + 3 * ARR_BYTES;

        #pragma unroll
        for (int ks = 0; ks < 2; ks++) {
            const int k = ks * 16;
            uint32_t a_hi[4][4], a_lo[4][4], b_hi[4][2], b_lo[4][2];
            #pragma unroll
            for (int mi = 0; mi < 4; mi++) {
                int rowb = wm * 64 + mi * 16 + r;
                uint32_t o00 = (uint32_t)rowb * (ROWP*2) + (uint32_t)(k + c2) * 2;
                a_hi[mi][0] = *(const uint32_t*)(pAh + o00);
                a_hi[mi][1] = *(const uint32_t*)(pAh + o00 + 8*(ROWP*2));
                a_hi[mi][2] = *(const uint32_t*)(pAh + o00 + 16);
                a_hi[mi][3] = *(const uint32_t*)(pAh + o00 + 8*(ROWP*2) + 16);
                a_lo[mi][0] = *(const uint32_t*)(pAl + o00);
                a_lo[mi][1] = *(const uint32_t*)(pAl + o00 + 8*(ROWP*2));
                a_lo[mi][2] = *(const uint32_t*)(pAl + o00 + 16);
                a_lo[mi][3] = *(const uint32_t*)(pAl + o00 + 8*(ROWP*2) + 16);
            }
            #pragma unroll
            for (int ni = 0; ni < 4; ni++) {
                int rowb = wn * 32 + ni * 8 + r;
                uint32_t o00 = (uint32_t)rowb * (ROWP*2) + (uint32_t)(k + c2) * 2;
                b_hi[ni][0] = *(const uint32_t*)(pBh + o00);
                b_hi[ni][1] = *(const uint32_t*)(pBh + o00 + 16);
                b_lo[ni][0] = *(const uint32_t*)(pBl + o00);
                b_lo[ni][1] = *(const uint32_t*)(pBl + o00 + 16);
            }
            // product-outermost: 16 independent accumulators between reuses
            #pragma unroll
            for (int mi = 0; mi < 4; mi++)
                #pragma unroll
                for (int ni = 0; ni < 4; ni++)
                    mma16816(acc[mi][ni], a_hi[mi], b_hi[ni]);
            #pragma unroll
            for (int mi = 0; mi < 4; mi++)
                #pragma unroll
                for (int ni = 0; ni < 4; ni++)
                    mma16816(acc[mi][ni], a_hi[mi], b_lo[ni]);
            #pragma unroll
            for (int mi = 0; mi < 4; mi++)
                #pragma unroll
                for (int ni = 0; ni < 4; ni++)
                    mma16816(acc[mi][ni], a_lo[mi], b_hi[ni]);
        }
        __syncthreads();
    }
#undef LOAD_STAGE

    // epilogue
    const float* bb = bias ? (bias + (size_t)bat * HH) : nullptr;
    float* Cb = C + (size_t)bat * strideC;
    #pragma unroll
    for (int ni = 0; ni < 4; ni++) {
        int col = n0 + wn * 32 + ni * 8 + c2;
        float bx = bb ? bb[col] : 0.f;
        float by = bb ? bb[col + 1] : 0.f;
        #pragma unroll
        for (int mi = 0; mi < 4; mi++) {
            int row = m0 + wm * 64 + mi * 16 + r;
            float2 v0 = make_float2(acc[mi][ni][0] + bx, acc[mi][ni][1] + by);
            float2 v1 = make_float2(acc[mi][ni][2] + bx, acc[mi][ni][3] + by);
            *(float2*)(Cb + (size_t)row * HH + col) = v0;
            *(float2*)(Cb + (size_t)(row + 8) * HH + col) = v1;
        }
    }
}

// ---------------- prologue: qbuf = question, h = 0 ----------------
__global__ void k_prologue(const float* __restrict__ question) {
    int t = blockIdx.x * 256 + threadIdx.x;
    if (t < BB*HH) { g_qbuf[t] = question[t]; g_hbuf[t] = 0.f; }
}

// ---------------- combined bias: bc[k][j] = pw_b[k] @ Ws_W[k] + Ws_b[k] ----------------
__global__ void k_bc(const float* __restrict__ pw_b, const float* __restrict__ Ws_W,
                     const float* __restrict__ Ws_b) {
    int k = blockIdx.x;
    int j = blockIdx.y * 256 + threadIdx.x;
    float acc = Ws_b[k*HH + j];
    const float* W = Ws_W + (size_t)k*HH*HH;
    const float* b = pw_b + k*HH;
    #pragma unroll 4
    for (int m = 0; m < HH; m++) acc = fmaf(b[m], W[(size_t)m*HH + j], acc);
    g_bc[k*HH + j] = acc;
}

// ---------------- W_ht = qbuf @ Wt_W[k] + Wt_b[k]  (k-split, atomic) ----------------
__global__ void k_init_wht(const float* __restrict__ Wt_b) {
    int t = blockIdx.x * 256 + threadIdx.x;
    if (t < KK*BB*HH) {
        int k = t / (BB*HH);
        int j = t % HH;
        g_Wht[t] = Wt_b[k*HH + j];
    }
}

__global__ void k_wht(const float* __restrict__ Wt_W) {
    int k  = blockIdx.x;
    int jc = blockIdx.y;
    int hs = blockIdx.z;
    int t  = threadIdx.x;
    int j  = jc*128 + t;
    int h0 = hs*128;
    __shared__ float qs[32][128];
    #pragma unroll 8
    for (int r = 0; r < 32; r++) qs[r][t] = g_qbuf[r*HH + h0 + t];
    __syncthreads();
    float acc[32];
    #pragma unroll
    for (int b = 0; b < 32; b++) acc[b] = 0.f;
    for (int hh = 0; hh < 128; hh++) {
        float w = Wt_W[((size_t)k*HH + h0 + hh)*HH + j];
        #pragma unroll
        for (int b = 0; b < 32; b++) acc[b] = fmaf(qs[b][hh], w, acc[b]);
    }
    #pragma unroll
    for (int b = 0; b < 32; b++) atomicAdd(&g_Wht[(k*BB + b)*HH + j], acc[b]);
}

// ---------------- scores[k,b,s] = We . tanh(W_hs + W_ht) + We_b ----------------
__global__ void k_scores(const float* __restrict__ WeW, const float* __restrict__ Web) {
    int kb = blockIdx.x;
    int sc = blockIdx.y;
    int k = kb / BB;
    __shared__ float sh[2*HH];
    for (int i = threadIdx.x; i < HH; i += 256) {
        sh[i]      = g_Wht[kb*HH + i];
        sh[HH + i] = WeW[k*HH + i];
    }
    __syncthreads();
    int warp = threadIdx.x >> 5, lane = threadIdx.x & 31;
    float web = Web[k];
    for (int s = sc*128 + warp; s < sc*128 + 128; s += 8) {
        const float* row = g_Whs + (((size_t)kb*SS + s))*HH;
        float sum = 0.f;
        #pragma unroll
        for (int i = 0; i < HH/32; i++) {
            int h = lane + i*32;
            float x = row[h] + sh[h];
            float e = __expf(2.f * x);
            float t = 1.f - __fdividef(2.f, e + 1.f);
            sum = fmaf(t, sh[HH + h], sum);
        }
        #pragma unroll
        for (int o = 16; o; o >>= 1) sum += __shfl_xor_sync(0xffffffffu, sum, o);
        if (lane == 0) g_scores[kb*SS + s] = sum + web;
    }
}

// ---------------- softmax over S, in place ----------------
__global__ void k_softmax() {
    __shared__ float red[256];
    int row = blockIdx.x;
    float* p = g_scores + (size_t)row * SS;
    int t = threadIdx.x;
    float a = p[t], b = p[t + 256];
    red[t] = fmaxf(a, b);
    __syncthreads();
    for (int o = 128; o; o >>= 1) { if (t < o) red[t] = fmaxf(red[t], red[t+o]); __syncthreads(); }
    float m = red[0];
    __syncthreads();
    float e0 = __expf(a - m), e1 = __expf(b - m);
    red[t] = e0 + e1;
    __syncthreads();
    for (int o = 128; o; o >>= 1) { if (t < o) red[t] += red[t+o]; __syncthreads(); }
    float inv = 1.f / red[0];
    p[t] = e0 * inv;
    p[t + 256] = e1 * inv;
}

// ---------------- alpha_linear, prob (hop 0), argmax ----------------
__global__ void k_alpha(const float* __restrict__ hw, const float* __restrict__ hb,
                        float* __restrict__ out_prob, int hop) {
    int b = blockIdx.x;
    int s = threadIdx.x;
    float al = hb[0];
    #pragma unroll
    for (int k = 0; k < KK; k++) al = fmaf(g_scores[(k*BB + b)*SS + s], hw[k], al);
    __shared__ float ssq[512];
    __shared__ float sval[512];
    __shared__ int   sidx[512];
    ssq[s] = al * al; sval[s] = al; sidx[s] = s;
    __syncthreads();
    for (int o = 256; o; o >>= 1) {
        if (s < o) {
            ssq[s] += ssq[s + o];
            float v2 = sval[s + o]; int i2 = sidx[s + o];
            if (v2 > sval[s] || (v2 == sval[s] && i2 < sidx[s])) { sval[s] = v2; sidx[s] = i2; }
        }
        __syncthreads();
    }
    if (s == 0) g_idx[b] = sidx[0];
    if (hop == 0) out_prob[b*SS + s] = al / sqrtf(ssq[0]);
}

// ---------------- GRU ----------------
__global__ void k_gru_init(const float* __restrict__ bih, const float* __restrict__ bhh) {
    int t = blockIdx.x * 256 + threadIdx.x;
    if (t < BB*H3) { int j = t % H3; g_GX[t] = bih[j]; g_GH[t] = bhh[j]; }
}

__global__ void k_grugemm(const float* __restrict__ Wih, const float* __restrict__ Whh,
                          const float* __restrict__ text) {
    int jc = blockIdx.x;
    int ks = blockIdx.y;
    int bg = blockIdx.z;
    int t = threadIdx.x;
    int j = jc*256 + t;
    int i0 = ks*256;
    __shared__ float xs[8][256];
    int i = i0 + t;
    #pragma unroll
    for (int r = 0; r < 8; r++) {
        int b = bg*8 + r;
        float v;
        if (i < 768)       v = g_qbuf[b*HH + i];
        else if (i < 1536) v = text[((size_t)b*SS + g_idx[b])*HH + (i - 768)];
        else               v = g_hbuf[b*HH + (i - 1536)];
        xs[r][t] = v;
    }
    __syncthreads();
    const float* W; int wi0; float* G;
    if (i0 < 1536) { W = Wih; wi0 = i0;        G = g_GX; }
    else           { W = Whh; wi0 = i0 - 1536; G = g_GH; }
    float acc[8];
    #pragma unroll
    for (int r = 0; r < 8; r++) acc[r] = 0.f;
    #pragma unroll 4
    for (int kk = 0; kk < 256; kk++) {
        float w = W[(size_t)(wi0 + kk)*H3 + j];
        #pragma unroll
        for (int r = 0; r < 8; r++) acc[r] = fmaf(xs[r][kk], w, acc[r]);
    }
    #pragma unroll
    for (int r = 0; r < 8; r++) atomicAdd(&G[(bg*8 + r)*H3 + j], acc[r]);
}

__global__ void k_grugate(float* __restrict__ out_h, int hop) {
    int t = blockIdx.x * 256 + threadIdx.x;
    if (t >= BB*HH) return;
    int b = t / HH, j = t % HH;
    float gxr = g_GX[b*H3 + j],        ghr = g_GH[b*H3 + j];
    float gxz = g_GX[b*H3 + HH + j],   ghz = g_GH[b*H3 + HH + j];
    float gxn = g_GX[b*H3 + 2*HH + j], ghn = g_GH[b*H3 + 2*HH + j];
    float r = 1.f / (1.f + expf(-(gxr + ghr)));
    float z = 1.f / (1.f + expf(-(gxz + ghz)));
    float n = tanhf(gxn + r * ghn);
    float hprev = g_hbuf[t];
    float hn = (1.f - z) * n + z * hprev;
    g_hbuf[t] = hn;
    g_qbuf[t] = hn;
    out_h[((size_t)b*HOPS + hop)*HH + j] = hn;
}

// ---------------- launch ----------------
extern "C" void kernel_launch(void* const* d_in, const int* in_sizes, int n_in,
                              void* d_out, int out_size) {
    const float* question = (const float*)d_in[0];
    const float* text     = (const float*)d_in[1];
    const float* pw_W     = (const float*)d_in[2];
    const float* pw_b     = (const float*)d_in[3];
    const float* Ws_W     = (const float*)d_in[4];
    const float* Ws_b     = (const float*)d_in[5];
    const float* Wt_W     = (const float*)d_in[6];
    const float* Wt_b     = (const float*)d_in[7];
    const float* We_W     = (const float*)d_in[8];
    const float* We_b     = (const float*)d_in[9];
    const float* headw_W  = (const float*)d_in[10];
    const float* headw_b  = (const float*)d_in[11];
    const float* gru_Wih  = (const float*)d_in[12];
    const float* gru_Whh  = (const float*)d_in[13];
    const float* gru_bih  = (const float*)d_in[14];
    const float* gru_bhh  = (const float*)d_in[15];

    float* out_prob = (float*)d_out;
    float* out_h    = (float*)d_out + BB*SS;

    float *p_Wc, *p_bc, *p_Whs;
    __nv_bfloat16 *p_tAhi, *p_tAlo, *p_pwhi, *p_pwlo, *p_WsThi, *p_WsTlo, *p_WcThi, *p_WcTlo;
    cudaGetSymbolAddress((void**)&p_Wc,    g_Wc);
    cudaGetSymbolAddress((void**)&p_bc,    g_bc);
    cudaGetSymbolAddress((void**)&p_Whs,   g_Whs);
    cudaGetSymbolAddress((void**)&p_tAhi,  g_tAhi);
    cudaGetSymbolAddress((void**)&p_tAlo,  g_tAlo);
    cudaGetSymbolAddress((void**)&p_pwhi,  g_pwhi);
    cudaGetSymbolAddress((void**)&p_pwlo,  g_pwlo);
    cudaGetSymbolAddress((void**)&p_WsThi, g_WsThi);
    cudaGetSymbolAddress((void**)&p_WsTlo, g_WsTlo);
    cudaGetSymbolAddress((void**)&p_WcThi, g_WcThi);
    cudaGetSymbolAddress((void**)&p_WcTlo, g_WcTlo);

    cudaFuncSetAttribute(k_hmma, cudaFuncAttributeMaxDynamicSharedMemorySize, HMMA_SMEM);

    k_prologue<<<(BB*HH + 255)/256, 256>>>(question);
    k_bc<<<dim3(KK, HH/256), 256>>>(pw_b, Ws_W, Ws_b);

    // split conversions
    k_split<<<(MROWS*HH + 255)/256, 256>>>(text, p_tAhi, p_tAlo, MROWS*HH);
    k_split<<<(KK*HH*HH + 255)/256, 256>>>(pw_W, p_pwhi, p_pwlo, KK*HH*HH);
    k_splitT<<<dim3(HH/32, HH/32, KK), dim3(32, 8)>>>(Ws_W, p_WsThi, p_WsTlo);

    // Wc[k] = pw_W[k] @ Ws_W[k]  (HMMA split-bf16)
    k_hmma<<<dim3(HH/128, HH/128, KK), 256, HMMA_SMEM>>>(
        p_pwhi, p_pwlo, (size_t)HH*HH,
        p_WsThi, p_WsTlo, (size_t)HH*HH,
        p_Wc, (size_t)HH*HH, nullptr, HH);

    k_splitT<<<dim3(HH/32, HH/32, KK), dim3(32, 8)>>>(p_Wc, p_WcThi, p_WcTlo);

    // W_hs[k] = text @ Wc[k] + bc[k]  (HMMA split-bf16)
    k_hmma<<<dim3(HH/128, MROWS/128, KK), 256, HMMA_SMEM>>>(
        p_tAhi, p_tAlo, 0,
        p_WcThi, p_WcTlo, (size_t)HH*HH,
        p_Whs, (size_t)MROWS*HH, p_bc, HH);

    for (int hop = 0; hop < HOPS; hop++) {
        k_init_wht<<<(KK*BB*HH + 255)/256, 256>>>(Wt_b);
        k_wht<<<dim3(KK, HH/128, HH/128), 128>>>(Wt_W);
        k_scores<<<dim3(KK*BB, SS/128), 256>>>(We_W, We_b);
        k_softmax<<<KK*BB, 256>>>();
        k_alpha<<<BB, 512>>>(headw_W, headw_b, out_prob, hop);
        k_gru_init<<<(BB*H3 + 255)/256, 256>>>(gru_bih, gru_bhh);
        k_grugemm<<<dim3(H3/256, H3/256, BB/8), 256>>>(gru_Wih, gru_Whh, text);
        k_grugate<<<(BB*HH + 255)/256, 256>>>(out_h, hop);
    }
}

// round 5
// speedup vs baseline: 1.7294x; 1.0455x over previous
#include <cuda_runtime.h>
#include <cuda_bf16.h>
#include <math.h>
#include <stdint.h>

#define BB 32
#define SS 512
#define HH 768
#define KK 4
#define HOPS 3
#define H2 1536
#define H3 2304
#define MROWS (BB*SS)

// ---------------- scratch (device globals; no allocation) ----------------
__device__ float g_Wc[(size_t)KK*HH*HH];
__device__ float g_bc[KK*HH];
__device__ float g_Whs[(size_t)KK*MROWS*HH];       // [K,B,S,H] 201MB
__device__ float g_Wht[KK*BB*HH];
__device__ float g_scores[KK*BB*SS];
__device__ float g_qbuf[BB*HH];
__device__ float g_hbuf[BB*HH];
__device__ float g_GX[BB*H3];
__device__ float g_GH[BB*H3];
__device__ int   g_idx[BB];
// split-bf16 operands
__device__ __nv_bfloat16 g_tAhi[(size_t)MROWS*HH];
__device__ __nv_bfloat16 g_tAlo[(size_t)MROWS*HH];
__device__ __nv_bfloat16 g_pwhi[(size_t)KK*HH*HH];
__device__ __nv_bfloat16 g_pwlo[(size_t)KK*HH*HH];
__device__ __nv_bfloat16 g_WsThi[(size_t)KK*HH*HH];
__device__ __nv_bfloat16 g_WsTlo[(size_t)KK*HH*HH];
__device__ __nv_bfloat16 g_WcThi[(size_t)KK*HH*HH];
__device__ __nv_bfloat16 g_WcTlo[(size_t)KK*HH*HH];

// ---------------- helpers ----------------
__device__ __forceinline__ uint32_t smem_u32(const void* p) {
    uint32_t a;
    asm("{ .reg .u64 t; cvta.to.shared.u64 t, %1; cvt.u32.u64 %0, t; }" : "=r"(a) : "l"(p));
    return a;
}
__device__ __forceinline__ void mma16816(float* d, const uint32_t* a, const uint32_t* b) {
    asm volatile("mma.sync.aligned.m16n8k16.row.col.f32.bf16.bf16.f32 "
        "{%0,%1,%2,%3},{%4,%5,%6,%7},{%8,%9},{%0,%1,%2,%3};"
        : "+f"(d[0]), "+f"(d[1]), "+f"(d[2]), "+f"(d[3])
        : "r"(a[0]), "r"(a[1]), "r"(a[2]), "r"(a[3]), "r"(b[0]), "r"(b[1]));
}
__device__ __forceinline__ void ldsm4(uint32_t* r, uint32_t addr) {
    asm volatile("ldmatrix.sync.aligned.m8n8.x4.shared.b16 {%0,%1,%2,%3}, [%4];"
        : "=r"(r[0]), "=r"(r[1]), "=r"(r[2]), "=r"(r[3]) : "r"(addr));
}
__device__ __forceinline__ void cp16(uint32_t dst, const void* src) {
    asm volatile("cp.async.cg.shared.global [%0], [%1], 16;" :: "r"(dst), "l"(src));
}
#define CP_COMMIT() asm volatile("cp.async.commit_group;" ::: "memory")
#define CP_WAIT1()  asm volatile("cp.async.wait_group 1;" ::: "memory")

// ---------------- split helpers ----------------
__device__ __forceinline__ void split2(float x, __nv_bfloat16& h, __nv_bfloat16& l) {
    __nv_bfloat16 hb = __float2bfloat16(x);
    h = hb;
    l = __float2bfloat16(x - __bfloat162float(hb));
}

__global__ void k_split(const float* __restrict__ src, __nv_bfloat16* __restrict__ dhi,
                        __nv_bfloat16* __restrict__ dlo, int n) {
    int i = blockIdx.x * 256 + threadIdx.x;
    if (i < n) split2(src[i], dhi[i], dlo[i]);
}

// transpose + split: src [R=768, C=768] per batch -> dst [C, R]
__global__ void k_splitT(const float* __restrict__ src, __nv_bfloat16* __restrict__ dhi,
                         __nv_bfloat16* __restrict__ dlo) {
    __shared__ float t[32][33];
    int b = blockIdx.z;
    const float* S = src + (size_t)b * HH * HH;
    __nv_bfloat16* Dh = dhi + (size_t)b * HH * HH;
    __nv_bfloat16* Dl = dlo + (size_t)b * HH * HH;
    int r0 = blockIdx.y * 32, c0 = blockIdx.x * 32;
    for (int rr = threadIdx.y; rr < 32; rr += 8)
        t[rr][threadIdx.x] = S[(size_t)(r0 + rr) * HH + c0 + threadIdx.x];
    __syncthreads();
    for (int rr = threadIdx.y; rr < 32; rr += 8) {
        float v = t[threadIdx.x][rr];
        size_t o = (size_t)(c0 + rr) * HH + r0 + threadIdx.x;
        split2(v, Dh[o], Dl[o]);
    }
}

// ---------------- HMMA split-bf16 GEMM v2 ----------------
// C[m,n] = sum_k A[m,k]*B[n,k] (+bias[n]); A [M,Kd] rm, B [N,Kd] rm, C ld=HH.
// BM=128, BN=256, BK=32; 8 warps 2x4; warp tile 64x64; 3-stage cp.async; ldmatrix.
#define ROWP 40                        // padded row length (bf16) -> conflict-free
#define ROWB (ROWP*2)                  // 80 bytes
#define AH_O 0
#define AL_O (128*ROWB)                // 10240
#define BH_O (2*128*ROWB)              // 20480
#define BL_O (BH_O + 256*ROWB)        // 40960
#define STG2 (BL_O + 256*ROWB)        // 61440
#define SMEM2 (3*STG2)                 // 184320

__global__ __launch_bounds__(256, 1)
void k_hmma2(const __nv_bfloat16* __restrict__ Ahi, const __nv_bfloat16* __restrict__ Alo,
             size_t strideA,
             const __nv_bfloat16* __restrict__ Bhi, const __nv_bfloat16* __restrict__ Blo,
             size_t strideB,
             float* __restrict__ C, size_t strideC,
             const float* __restrict__ bias, int Kd)
{
    extern __shared__ char smem[];
    const uint32_t sb = smem_u32(smem);
    const int tid = threadIdx.x;
    const int lane = tid & 31;
    const int warp = tid >> 5;
    const int wm = warp >> 2, wn = warp & 3;      // 2 x 4 warps, warp tile 64x64
    const int bat = blockIdx.z;
    const int m0 = blockIdx.y * 128;
    const int n0 = blockIdx.x * 256;

    // ---- cp.async setup: 3072 16B chunks/stage, 12 per thread ----
    const __nv_bfloat16* gsrc[12];
    uint32_t dsto[12];
    {
        const __nv_bfloat16* baseA_h = Ahi + (size_t)bat * strideA + (size_t)m0 * Kd;
        const __nv_bfloat16* baseA_l = Alo + (size_t)bat * strideA + (size_t)m0 * Kd;
        const __nv_bfloat16* baseB_h = Bhi + (size_t)bat * strideB + (size_t)n0 * Kd;
        const __nv_bfloat16* baseB_l = Blo + (size_t)bat * strideB + (size_t)n0 * Kd;
        #pragma unroll
        for (int i = 0; i < 12; i++) {
            int id = i * 256 + tid;
            int cj = id & 3;
            int rid = id >> 2;                     // 0..767
            const __nv_bfloat16* bp; uint32_t ao; int row;
            if (rid < 128)      { bp = baseA_h; ao = AH_O; row = rid; }
            else if (rid < 256) { bp = baseA_l; ao = AL_O; row = rid - 128; }
            else if (rid < 512) { bp = baseB_h; ao = BH_O; row = rid - 256; }
            else                { bp = baseB_l; ao = BL_O; row = rid - 512; }
            gsrc[i] = bp + (size_t)row * Kd + cj * 8;
            dsto[i] = ao + (uint32_t)row * ROWB + (uint32_t)cj * 16;
        }
    }

    float acc[4][8][4];
    #pragma unroll
    for (int mi = 0; mi < 4; mi++)
        #pragma unroll
        for (int ni = 0; ni < 8; ni++)
            #pragma unroll
            for (int j = 0; j < 4; j++) acc[mi][ni][j] = 0.f;

    const int nIt = Kd / 32;

#define LOAD_STAGE2(it) do {                                  \
        uint32_t s_ = sb + ((it) % 3) * STG2;                 \
        int ko_ = (it) * 32;                                  \
        _Pragma("unroll")                                     \
        for (int i_ = 0; i_ < 12; i_++)                       \
            cp16(s_ + dsto[i_], gsrc[i_] + ko_);              \
        CP_COMMIT();                                          \
    } while (0)

    LOAD_STAGE2(0);
    LOAD_STAGE2(1);

    // ldmatrix per-lane address components
    const int grp = lane >> 3, lr = lane & 7;
    // A tiles: row = wm*64 + mi*16 + (grp&1)*8 + lr ; col byte = k*2 + (grp>>1)*16
    const uint32_t aoff = (uint32_t)(wm * 64 + (grp & 1) * 8 + lr) * ROWB + (uint32_t)(grp >> 1) * 16;
    // B tile pairs: row = wn*64 + pg*16 + (grp>>1)*8 + lr ; col byte = k*2 + (grp&1)*16
    const uint32_t boff = (uint32_t)(wn * 64 + (grp >> 1) * 8 + lr) * ROWB + (uint32_t)(grp & 1) * 16;

    for (int it = 0; it < nIt; ++it) {
        CP_WAIT1();
        __syncthreads();
        if (it + 2 < nIt) LOAD_STAGE2(it + 2);

        const uint32_t st = sb + (it % 3) * STG2;
        const uint32_t pAh = st + AH_O + aoff;
        const uint32_t pAl = st + AL_O + aoff;
        const uint32_t pBh = st + BH_O + boff;
        const uint32_t pBl = st + BL_O + boff;

        #pragma unroll
        for (int ks = 0; ks < 2; ks++) {
            const uint32_t kb2 = ks * 32;          // k*2 bytes
            uint32_t ah[4][4], al[4][4];
            #pragma unroll
            for (int mi = 0; mi < 4; mi++) {
                ldsm4(ah[mi], pAh + (uint32_t)mi * (16 * ROWB) + kb2);
                ldsm4(al[mi], pAl + (uint32_t)mi * (16 * ROWB) + kb2);
            }
            #pragma unroll
            for (int pg = 0; pg < 4; pg++) {
                uint32_t bh[4], bl[4];
                ldsm4(bh, pBh + (uint32_t)pg * (16 * ROWB) + kb2);
                ldsm4(bl, pBl + (uint32_t)pg * (16 * ROWB) + kb2);
                #pragma unroll
                for (int mi = 0; mi < 4; mi++) {
                    mma16816(acc[mi][2*pg],   ah[mi], bh);
                    mma16816(acc[mi][2*pg+1], ah[mi], bh + 2);
                }
                #pragma unroll
                for (int mi = 0; mi < 4; mi++) {
                    mma16816(acc[mi][2*pg],   ah[mi], bl);
                    mma16816(acc[mi][2*pg+1], ah[mi], bl + 2);
                }
                #pragma unroll
                for (int mi = 0; mi < 4; mi++) {
                    mma16816(acc[mi][2*pg],   al[mi], bh);
                    mma16816(acc[mi][2*pg+1], al[mi], bh + 2);
                }
            }
        }
        __syncthreads();
    }
#undef LOAD_STAGE2

    // epilogue
    const int r = lane >> 2, c2 = (lane & 3) * 2;
    const float* bb = bias ? (bias + (size_t)bat * HH) : nullptr;
    float* Cb = C + (size_t)bat * strideC;
    #pragma unroll
    for (int ni = 0; ni < 8; ni++) {
        int col = n0 + wn * 64 + ni * 8 + c2;
        float bx = bb ? bb[col] : 0.f;
        float by = bb ? bb[col + 1] : 0.f;
        #pragma unroll
        for (int mi = 0; mi < 4; mi++) {
            int row = m0 + wm * 64 + mi * 16 + r;
            float2 v0 = make_float2(acc[mi][ni][0] + bx, acc[mi][ni][1] + by);
            float2 v1 = make_float2(acc[mi][ni][2] + bx, acc[mi][ni][3] + by);
            *(float2*)(Cb + (size_t)row * HH + col) = v0;
            *(float2*)(Cb + (size_t)(row + 8) * HH + col) = v1;
        }
    }
}

// ---------------- prologue: qbuf = question, h = 0 ----------------
__global__ void k_prologue(const float* __restrict__ question) {
    int t = blockIdx.x * 256 + threadIdx.x;
    if (t < BB*HH) { g_qbuf[t] = question[t]; g_hbuf[t] = 0.f; }
}

// ---------------- combined bias: bc[k][j] = pw_b[k] @ Ws_W[k] + Ws_b[k] ----------------
__global__ void k_bc(const float* __restrict__ pw_b, const float* __restrict__ Ws_W,
                     const float* __restrict__ Ws_b) {
    int k = blockIdx.x;
    int j = blockIdx.y * 256 + threadIdx.x;
    float acc = Ws_b[k*HH + j];
    const float* W = Ws_W + (size_t)k*HH*HH;
    const float* b = pw_b + k*HH;
    #pragma unroll 4
    for (int m = 0; m < HH; m++) acc = fmaf(b[m], W[(size_t)m*HH + j], acc);
    g_bc[k*HH + j] = acc;
}

// ---------------- W_ht = qbuf @ Wt_W[k] + Wt_b[k]  (k-split, atomic) ----------------
__global__ void k_init_wht(const float* __restrict__ Wt_b) {
    int t = blockIdx.x * 256 + threadIdx.x;
    if (t < KK*BB*HH) {
        int k = t / (BB*HH);
        int j = t % HH;
        g_Wht[t] = Wt_b[k*HH + j];
    }
}

__global__ void k_wht(const float* __restrict__ Wt_W) {
    int k  = blockIdx.x;
    int jc = blockIdx.y;
    int hs = blockIdx.z;
    int t  = threadIdx.x;
    int j  = jc*128 + t;
    int h0 = hs*128;
    __shared__ float qs[32][128];
    #pragma unroll 8
    for (int r = 0; r < 32; r++) qs[r][t] = g_qbuf[r*HH + h0 + t];
    __syncthreads();
    float acc[32];
    #pragma unroll
    for (int b = 0; b < 32; b++) acc[b] = 0.f;
    for (int hh = 0; hh < 128; hh++) {
        float w = Wt_W[((size_t)k*HH + h0 + hh)*HH + j];
        #pragma unroll
        for (int b = 0; b < 32; b++) acc[b] = fmaf(qs[b][hh], w, acc[b]);
    }
    #pragma unroll
    for (int b = 0; b < 32; b++) atomicAdd(&g_Wht[(k*BB + b)*HH + j], acc[b]);
}

// ---------------- scores[k,b,s] = We . tanh(W_hs + W_ht) + We_b ----------------
__global__ __launch_bounds__(256)
void k_scores(const float* __restrict__ WeW, const float* __restrict__ Web) {
    int kb = blockIdx.x;
    int sc = blockIdx.y;
    int k = kb / BB;
    __shared__ float4 shW[HH/4];
    __shared__ float4 shE[HH/4];
    if (threadIdx.x < HH/4) {
        shW[threadIdx.x] = ((const float4*)(g_Wht + (size_t)kb*HH))[threadIdx.x];
        shE[threadIdx.x] = ((const float4*)(WeW + (size_t)k*HH))[threadIdx.x];
    }
    __syncthreads();
    int warp = threadIdx.x >> 5, lane = threadIdx.x & 31;
    float web = Web[k];
    for (int s = sc*128 + warp; s < sc*128 + 128; s += 8) {
        const float4* row = (const float4*)(g_Whs + ((size_t)kb*SS + s)*HH);
        float sum = 0.f;
        #pragma unroll
        for (int i = 0; i < 6; i++) {
            int idx = lane + i*32;
            float4 v = row[idx];
            float4 w = shW[idx];
            float4 e = shE[idx];
            float x0 = v.x + w.x, x1 = v.y + w.y, x2 = v.z + w.z, x3 = v.w + w.w;
            float t0 = 1.f - __fdividef(2.f, __expf(2.f*x0) + 1.f);
            float t1 = 1.f - __fdividef(2.f, __expf(2.f*x1) + 1.f);
            float t2 = 1.f - __fdividef(2.f, __expf(2.f*x2) + 1.f);
            float t3 = 1.f - __fdividef(2.f, __expf(2.f*x3) + 1.f);
            sum = fmaf(t0, e.x, sum);
            sum = fmaf(t1, e.y, sum);
            sum = fmaf(t2, e.z, sum);
            sum = fmaf(t3, e.w, sum);
        }
        #pragma unroll
        for (int o = 16; o; o >>= 1) sum += __shfl_xor_sync(0xffffffffu, sum, o);
        if (lane == 0) g_scores[kb*SS + s] = sum + web;
    }
}

// ---------------- softmax over S, in place ----------------
__global__ void k_softmax() {
    __shared__ float red[256];
    int row = blockIdx.x;
    float* p = g_scores + (size_t)row * SS;
    int t = threadIdx.x;
    float a = p[t], b = p[t + 256];
    red[t] = fmaxf(a, b);
    __syncthreads();
    for (int o = 128; o; o >>= 1) { if (t < o) red[t] = fmaxf(red[t], red[t+o]); __syncthreads(); }
    float m = red[0];
    __syncthreads();
    float e0 = __expf(a - m), e1 = __expf(b - m);
    red[t] = e0 + e1;
    __syncthreads();
    for (int o = 128; o; o >>= 1) { if (t < o) red[t] += red[t+o]; __syncthreads(); }
    float inv = 1.f / red[0];
    p[t] = e0 * inv;
    p[t + 256] = e1 * inv;
}

// ---------------- alpha_linear, prob (hop 0), argmax ----------------
__global__ void k_alpha(const float* __restrict__ hw, const float* __restrict__ hb,
                        float* __restrict__ out_prob, int hop) {
    int b = blockIdx.x;
    int s = threadIdx.x;
    float al = hb[0];
    #pragma unroll
    for (int k = 0; k < KK; k++) al = fmaf(g_scores[(k*BB + b)*SS + s], hw[k], al);
    __shared__ float ssq[512];
    __shared__ float sval[512];
    __shared__ int   sidx[512];
    ssq[s] = al * al; sval[s] = al; sidx[s] = s;
    __syncthreads();
    for (int o = 256; o; o >>= 1) {
        if (s < o) {
            ssq[s] += ssq[s + o];
            float v2 = sval[s + o]; int i2 = sidx[s + o];
            if (v2 > sval[s] || (v2 == sval[s] && i2 < sidx[s])) { sval[s] = v2; sidx[s] = i2; }
        }
        __syncthreads();
    }
    if (s == 0) g_idx[b] = sidx[0];
    if (hop == 0) out_prob[b*SS + s] = al / sqrtf(ssq[0]);
}

// ---------------- GRU ----------------
__global__ void k_gru_init(const float* __restrict__ bih, const float* __restrict__ bhh) {
    int t = blockIdx.x * 256 + threadIdx.x;
    if (t < BB*H3) { int j = t % H3; g_GX[t] = bih[j]; g_GH[t] = bhh[j]; }
}

__global__ void k_grugemm(const float* __restrict__ Wih, const float* __restrict__ Whh,
                          const float* __restrict__ text) {
    int jc = blockIdx.x;
    int ks = blockIdx.y;
    int bg = blockIdx.z;
    int t = threadIdx.x;
    int j = jc*256 + t;
    int i0 = ks*256;
    __shared__ float xs[8][256];
    int i = i0 + t;
    #pragma unroll
    for (int r = 0; r < 8; r++) {
        int b = bg*8 + r;
        float v;
        if (i < 768)       v = g_qbuf[b*HH + i];
        else if (i < 1536) v = text[((size_t)b*SS + g_idx[b])*HH + (i - 768)];
        else               v = g_hbuf[b*HH + (i - 1536)];
        xs[r][t] = v;
    }
    __syncthreads();
    const float* W; int wi0; float* G;
    if (i0 < 1536) { W = Wih; wi0 = i0;        G = g_GX; }
    else           { W = Whh; wi0 = i0 - 1536; G = g_GH; }
    float acc[8];
    #pragma unroll
    for (int r = 0; r < 8; r++) acc[r] = 0.f;
    #pragma unroll 4
    for (int kk = 0; kk < 256; kk++) {
        float w = W[(size_t)(wi0 + kk)*H3 + j];
        #pragma unroll
        for (int r = 0; r < 8; r++) acc[r] = fmaf(xs[r][kk], w, acc[r]);
    }
    #pragma unroll
    for (int r = 0; r < 8; r++) atomicAdd(&G[(bg*8 + r)*H3 + j], acc[r]);
}

__global__ void k_grugate(float* __restrict__ out_h, int hop) {
    int t = blockIdx.x * 256 + threadIdx.x;
    if (t >= BB*HH) return;
    int b = t / HH, j = t % HH;
    float gxr = g_GX[b*H3 + j],        ghr = g_GH[b*H3 + j];
    float gxz = g_GX[b*H3 + HH + j],   ghz = g_GH[b*H3 + HH + j];
    float gxn = g_GX[b*H3 + 2*HH + j], ghn = g_GH[b*H3 + 2*HH + j];
    float r = 1.f / (1.f + expf(-(gxr + ghr)));
    float z = 1.f / (1.f + expf(-(gxz + ghz)));
    float n = tanhf(gxn + r * ghn);
    float hprev = g_hbuf[t];
    float hn = (1.f - z) * n + z * hprev;
    g_hbuf[t] = hn;
    g_qbuf[t] = hn;
    out_h[((size_t)b*HOPS + hop)*HH + j] = hn;
}

// ---------------- launch ----------------
extern "C" void kernel_launch(void* const* d_in, const int* in_sizes, int n_in,
                              void* d_out, int out_size) {
    const float* question = (const float*)d_in[0];
    const float* text     = (const float*)d_in[1];
    const float* pw_W     = (const float*)d_in[2];
    const float* pw_b     = (const float*)d_in[3];
    const float* Ws_W     = (const float*)d_in[4];
    const float* Ws_b     = (const float*)d_in[5];
    const float* Wt_W     = (const float*)d_in[6];
    const float* Wt_b     = (const float*)d_in[7];
    const float* We_W     = (const float*)d_in[8];
    const float* We_b     = (const float*)d_in[9];
    const float* headw_W  = (const float*)d_in[10];
    const float* headw_b  = (const float*)d_in[11];
    const float* gru_Wih  = (const float*)d_in[12];
    const float* gru_Whh  = (const float*)d_in[13];
    const float* gru_bih  = (const float*)d_in[14];
    const float* gru_bhh  = (const float*)d_in[15];

    float* out_prob = (float*)d_out;
    float* out_h    = (float*)d_out + BB*SS;

    float *p_Wc, *p_bc, *p_Whs;
    __nv_bfloat16 *p_tAhi, *p_tAlo, *p_pwhi, *p_pwlo, *p_WsThi, *p_WsTlo, *p_WcThi, *p_WcTlo;
    cudaGetSymbolAddress((void**)&p_Wc,    g_Wc);
    cudaGetSymbolAddress((void**)&p_bc,    g_bc);
    cudaGetSymbolAddress((void**)&p_Whs,   g_Whs);
    cudaGetSymbolAddress((void**)&p_tAhi,  g_tAhi);
    cudaGetSymbolAddress((void**)&p_tAlo,  g_tAlo);
    cudaGetSymbolAddress((void**)&p_pwhi,  g_pwhi);
    cudaGetSymbolAddress((void**)&p_pwlo,  g_pwlo);
    cudaGetSymbolAddress((void**)&p_WsThi, g_WsThi);
    cudaGetSymbolAddress((void**)&p_WsTlo, g_WsTlo);
    cudaGetSymbolAddress((void**)&p_WcThi, g_WcThi);
    cudaGetSymbolAddress((void**)&p_WcTlo, g_WcTlo);

    cudaFuncSetAttribute(k_hmma2, cudaFuncAttributeMaxDynamicSharedMemorySize, SMEM2);

    k_prologue<<<(BB*HH + 255)/256, 256>>>(question);
    k_bc<<<dim3(KK, HH/256), 256>>>(pw_b, Ws_W, Ws_b);

    // split conversions
    k_split<<<(MROWS*HH + 255)/256, 256>>>(text, p_tAhi, p_tAlo, MROWS*HH);
    k_split<<<(KK*HH*HH + 255)/256, 256>>>(pw_W, p_pwhi, p_pwlo, KK*HH*HH);
    k_splitT<<<dim3(HH/32, HH/32, KK), dim3(32, 8)>>>(Ws_W, p_WsThi, p_WsTlo);

    // Wc[k] = pw_W[k] @ Ws_W[k]  (HMMA split-bf16)
    k_hmma2<<<dim3(HH/256, HH/128, KK), 256, SMEM2>>>(
        p_pwhi, p_pwlo, (size_t)HH*HH,
        p_WsThi, p_WsTlo, (size_t)HH*HH,
        p_Wc, (size_t)HH*HH, nullptr, HH);

    k_splitT<<<dim3(HH/32, HH/32, KK), dim3(32, 8)>>>(p_Wc, p_WcThi, p_WcTlo);

    // W_hs[k] = text @ Wc[k] + bc[k]  (HMMA split-bf16)
    k_hmma2<<<dim3(HH/256, MROWS/128, KK), 256, SMEM2>>>(
        p_tAhi, p_tAlo, 0,
        p_WcThi, p_WcTlo, (size_t)HH*HH,
        p_Whs, (size_t)MROWS*HH, p_bc, HH);

    for (int hop = 0; hop < HOPS; hop++) {
        k_init_wht<<<(KK*BB*HH + 255)/256, 256>>>(Wt_b);
        k_wht<<<dim3(KK, HH/128, HH/128), 128>>>(Wt_W);
        k_scores<<<dim3(KK*BB, SS/128), 256>>>(We_W, We_b);
        k_softmax<<<KK*BB, 256>>>();
        k_alpha<<<BB, 512>>>(headw_W, headw_b, out_prob, hop);
        k_gru_init<<<(BB*H3 + 255)/256, 256>>>(gru_bih, gru_bhh);
        k_grugemm<<<dim3(H3/256, H3/256, BB/8), 256>>>(gru_Wih, gru_Whh, text);
        k_grugate<<<(BB*HH + 255)/256, 256>>>(out_h, hop);
    }
}

// round 6
// speedup vs baseline: 1.9166x; 1.1083x over previous
#include <cuda_runtime.h>
#include <cuda_bf16.h>
#include <math.h>
#include <stdint.h>

#define BB 32
#define SS 512
#define HH 768
#define KK 4
#define HOPS 3
#define H2 1536
#define H3 2304
#define MROWS (BB*SS)

// ---------------- scratch (device globals; no allocation) ----------------
__device__ float g_Wc[(size_t)KK*HH*HH];
__device__ float g_bc[KK*HH];
__device__ float g_Whs[(size_t)KK*MROWS*HH];       // [K,B,S,H] 201MB
__device__ float g_Wht[KK*BB*HH];
__device__ float g_scores[KK*BB*SS];
__device__ float g_qbuf[BB*HH];
__device__ float g_hbuf[BB*HH];
__device__ float g_GX[BB*H3];
__device__ float g_GH[BB*H3];
__device__ int   g_idx[BB];
// split-bf16 operands
__device__ __nv_bfloat16 g_tAhi[(size_t)MROWS*HH];
__device__ __nv_bfloat16 g_tAlo[(size_t)MROWS*HH];
__device__ __nv_bfloat16 g_pwhi[(size_t)KK*HH*HH];
__device__ __nv_bfloat16 g_pwlo[(size_t)KK*HH*HH];
__device__ __nv_bfloat16 g_WsThi[(size_t)KK*HH*HH];
__device__ __nv_bfloat16 g_WsTlo[(size_t)KK*HH*HH];
__device__ __nv_bfloat16 g_WcThi[(size_t)KK*HH*HH];
__device__ __nv_bfloat16 g_WcTlo[(size_t)KK*HH*HH];

// ---------------- helpers ----------------
__device__ __forceinline__ uint32_t smem_u32(const void* p) {
    uint32_t a;
    asm("{ .reg .u64 t; cvta.to.shared.u64 t, %1; cvt.u32.u64 %0, t; }" : "=r"(a) : "l"(p));
    return a;
}
__device__ __forceinline__ void mma16816(float* d, const uint32_t* a, const uint32_t* b) {
    asm volatile("mma.sync.aligned.m16n8k16.row.col.f32.bf16.bf16.f32 "
        "{%0,%1,%2,%3},{%4,%5,%6,%7},{%8,%9},{%0,%1,%2,%3};"
        : "+f"(d[0]), "+f"(d[1]), "+f"(d[2]), "+f"(d[3])
        : "r"(a[0]), "r"(a[1]), "r"(a[2]), "r"(a[3]), "r"(b[0]), "r"(b[1]));
}
__device__ __forceinline__ void ldsm4(uint32_t* r, uint32_t addr) {
    asm volatile("ldmatrix.sync.aligned.m8n8.x4.shared.b16 {%0,%1,%2,%3}, [%4];"
        : "=r"(r[0]), "=r"(r[1]), "=r"(r[2]), "=r"(r[3]) : "r"(addr));
}
__device__ __forceinline__ void cp16(uint32_t dst, const void* src) {
    asm volatile("cp.async.cg.shared.global [%0], [%1], 16;" :: "r"(dst), "l"(src));
}
#define CP_COMMIT() asm volatile("cp.async.commit_group;" ::: "memory")
#define CP_WAIT0()  asm volatile("cp.async.wait_group 0;" ::: "memory")

// ---------------- split helpers ----------------
__device__ __forceinline__ void split2(float x, __nv_bfloat16& h, __nv_bfloat16& l) {
    __nv_bfloat16 hb = __float2bfloat16(x);
    h = hb;
    l = __float2bfloat16(x - __bfloat162float(hb));
}

__global__ void k_split(const float* __restrict__ src, __nv_bfloat16* __restrict__ dhi,
                        __nv_bfloat16* __restrict__ dlo, int n) {
    int i = blockIdx.x * 256 + threadIdx.x;
    if (i < n) split2(src[i], dhi[i], dlo[i]);
}

// transpose + split: src [R=768, C=768] per batch -> dst [C, R]
__global__ void k_splitT(const float* __restrict__ src, __nv_bfloat16* __restrict__ dhi,
                         __nv_bfloat16* __restrict__ dlo) {
    __shared__ float t[32][33];
    int b = blockIdx.z;
    const float* S = src + (size_t)b * HH * HH;
    __nv_bfloat16* Dh = dhi + (size_t)b * HH * HH;
    __nv_bfloat16* Dl = dlo + (size_t)b * HH * HH;
    int r0 = blockIdx.y * 32, c0 = blockIdx.x * 32;
    for (int rr = threadIdx.y; rr < 32; rr += 8)
        t[rr][threadIdx.x] = S[(size_t)(r0 + rr) * HH + c0 + threadIdx.x];
    __syncthreads();
    for (int rr = threadIdx.y; rr < 32; rr += 8) {
        float v = t[threadIdx.x][rr];
        size_t o = (size_t)(c0 + rr) * HH + r0 + threadIdx.x;
        split2(v, Dh[o], Dl[o]);
    }
}

// ---------------- HMMA split-bf16 GEMM v3: 2 CTAs/SM ----------------
// C[m,n] = sum_k A[m,k]*B[n,k] (+bias[n]); A [M,Kd] rm, B [N,Kd] rm, C ld=HH.
// BM=128, BN=128, BK=32; 8 warps 2x4; warp tile 64x32; 2-stage cp.async;
// ldmatrix; one barrier per chunk; smem 80KB/CTA -> 2 CTAs resident.
#define ROWP 40                        // padded row length (bf16) -> conflict-free
#define ROWB (ROWP*2)                  // 80 bytes
#define ARRB (128*ROWB)                // 10240 per array
#define STG3 (4*ARRB)                  // 40960 per stage
#define SMEM3 (2*STG3)                 // 81920

__global__ __launch_bounds__(256, 2)
void k_hmma3(const __nv_bfloat16* __restrict__ Ahi, const __nv_bfloat16* __restrict__ Alo,
             size_t strideA,
             const __nv_bfloat16* __restrict__ Bhi, const __nv_bfloat16* __restrict__ Blo,
             size_t strideB,
             float* __restrict__ C, size_t strideC,
             const float* __restrict__ bias, int Kd)
{
    extern __shared__ char smem[];
    const uint32_t sb = smem_u32(smem);
    const int tid = threadIdx.x;
    const int lane = tid & 31;
    const int warp = tid >> 5;
    const int wm = warp >> 2, wn = warp & 3;      // 2 x 4 warps, warp tile 64x32
    const int bat = blockIdx.z;
    const int m0 = blockIdx.y * 128;
    const int n0 = blockIdx.x * 128;

    // cp.async: 2048 16B chunks/stage = 8/thread: 4 arrays x rows {r0, r0+64}
    const int r0 = tid >> 2, cj = tid & 3;
    const __nv_bfloat16* bAh = Ahi + (size_t)bat * strideA + (size_t)m0 * Kd + (size_t)r0 * Kd + cj * 8;
    const __nv_bfloat16* bAl = Alo + (size_t)bat * strideA + (size_t)m0 * Kd + (size_t)r0 * Kd + cj * 8;
    const __nv_bfloat16* bBh = Bhi + (size_t)bat * strideB + (size_t)n0 * Kd + (size_t)r0 * Kd + cj * 8;
    const __nv_bfloat16* bBl = Blo + (size_t)bat * strideB + (size_t)n0 * Kd + (size_t)r0 * Kd + cj * 8;
    const size_t rstep = (size_t)64 * Kd;
    const uint32_t d0 = (uint32_t)r0 * ROWB + (uint32_t)cj * 16;
    const uint32_t d1 = d0 + 64 * ROWB;

    float acc[4][4][4];
    #pragma unroll
    for (int mi = 0; mi < 4; mi++)
        #pragma unroll
        for (int ni = 0; ni < 4; ni++)
            #pragma unroll
            for (int j = 0; j < 4; j++) acc[mi][ni][j] = 0.f;

    const int nIt = Kd / 32;

#define LOAD3(it) do {                                            \
        uint32_t s_ = sb + ((it) & 1) * STG3;                     \
        int ko_ = (it) * 32;                                      \
        cp16(s_ + 0*ARRB + d0, bAh + ko_);                        \
        cp16(s_ + 0*ARRB + d1, bAh + rstep + ko_);                \
        cp16(s_ + 1*ARRB + d0, bAl + ko_);                        \
        cp16(s_ + 1*ARRB + d1, bAl + rstep + ko_);                \
        cp16(s_ + 2*ARRB + d0, bBh + ko_);                        \
        cp16(s_ + 2*ARRB + d1, bBh + rstep + ko_);                \
        cp16(s_ + 3*ARRB + d0, bBl + ko_);                        \
        cp16(s_ + 3*ARRB + d1, bBl + rstep + ko_);                \
        CP_COMMIT();                                              \
    } while (0)

    LOAD3(0);

    // ldmatrix per-lane address components
    const int grp = lane >> 3, lr = lane & 7;
    const uint32_t aoff = (uint32_t)(wm * 64 + (grp & 1) * 8 + lr) * ROWB + (uint32_t)(grp >> 1) * 16;
    const uint32_t boff = (uint32_t)(wn * 32 + (grp >> 1) * 8 + lr) * ROWB + (uint32_t)(grp & 1) * 16;

    for (int it = 0; it < nIt; ++it) {
        CP_WAIT0();
        __syncthreads();
        if (it + 1 < nIt) LOAD3(it + 1);

        const uint32_t st = sb + (it & 1) * STG3;
        const uint32_t pAh = st + 0*ARRB + aoff;
        const uint32_t pAl = st + 1*ARRB + aoff;
        const uint32_t pBh = st + 2*ARRB + boff;
        const uint32_t pBl = st + 3*ARRB + boff;

        #pragma unroll
        for (int ks = 0; ks < 2; ks++) {
            const uint32_t kb2 = ks * 32;          // k*2 bytes
            uint32_t ah[4][4], al[4][4];
            #pragma unroll
            for (int mi = 0; mi < 4; mi++) {
                ldsm4(ah[mi], pAh + (uint32_t)mi * (16 * ROWB) + kb2);
                ldsm4(al[mi], pAl + (uint32_t)mi * (16 * ROWB) + kb2);
            }
            #pragma unroll
            for (int pg = 0; pg < 2; pg++) {
                uint32_t bh[4], bl[4];
                ldsm4(bh, pBh + (uint32_t)pg * (16 * ROWB) + kb2);
                ldsm4(bl, pBl + (uint32_t)pg * (16 * ROWB) + kb2);
                #pragma unroll
                for (int mi = 0; mi < 4; mi++) {
                    mma16816(acc[mi][2*pg],   ah[mi], bh);
                    mma16816(acc[mi][2*pg+1], ah[mi], bh + 2);
                }
                #pragma unroll
                for (int mi = 0; mi < 4; mi++) {
                    mma16816(acc[mi][2*pg],   ah[mi], bl);
                    mma16816(acc[mi][2*pg+1], ah[mi], bl + 2);
                }
                #pragma unroll
                for (int mi = 0; mi < 4; mi++) {
                    mma16816(acc[mi][2*pg],   al[mi], bh);
                    mma16816(acc[mi][2*pg+1], al[mi], bh + 2);
                }
            }
        }
    }
#undef LOAD3

    // epilogue
    const int r = lane >> 2, c2 = (lane & 3) * 2;
    const float* bb = bias ? (bias + (size_t)bat * HH) : nullptr;
    float* Cb = C + (size_t)bat * strideC;
    #pragma unroll
    for (int ni = 0; ni < 4; ni++) {
        int col = n0 + wn * 32 + ni * 8 + c2;
        float bx = bb ? bb[col] : 0.f;
        float by = bb ? bb[col + 1] : 0.f;
        #pragma unroll
        for (int mi = 0; mi < 4; mi++) {
            int row = m0 + wm * 64 + mi * 16 + r;
            float2 v0 = make_float2(acc[mi][ni][0] + bx, acc[mi][ni][1] + by);
            float2 v1 = make_float2(acc[mi][ni][2] + bx, acc[mi][ni][3] + by);
            *(float2*)(Cb + (size_t)row * HH + col) = v0;
            *(float2*)(Cb + (size_t)(row + 8) * HH + col) = v1;
        }
    }
}

// ---------------- prologue: qbuf = question, h = 0 ----------------
__global__ void k_prologue(const float* __restrict__ question) {
    int t = blockIdx.x * 256 + threadIdx.x;
    if (t < BB*HH) { g_qbuf[t] = question[t]; g_hbuf[t] = 0.f; }
}

// ---------------- combined bias: bc[k][j] = pw_b[k] @ Ws_W[k] + Ws_b[k] ----------------
__global__ void k_bc(const float* __restrict__ pw_b, const float* __restrict__ Ws_W,
                     const float* __restrict__ Ws_b) {
    int k = blockIdx.x;
    int j = blockIdx.y * 256 + threadIdx.x;
    float acc = Ws_b[k*HH + j];
    const float* W = Ws_W + (size_t)k*HH*HH;
    const float* b = pw_b + k*HH;
    #pragma unroll 4
    for (int m = 0; m < HH; m++) acc = fmaf(b[m], W[(size_t)m*HH + j], acc);
    g_bc[k*HH + j] = acc;
}

// ---------------- W_ht = qbuf @ Wt_W[k] + Wt_b[k]  (k-split, atomic) ----------------
__global__ void k_init_wht(const float* __restrict__ Wt_b) {
    int t = blockIdx.x * 256 + threadIdx.x;
    if (t < KK*BB*HH) {
        int k = t / (BB*HH);
        int j = t % HH;
        g_Wht[t] = Wt_b[k*HH + j];
    }
}

__global__ void k_wht(const float* __restrict__ Wt_W) {
    int k  = blockIdx.x;
    int jc = blockIdx.y;
    int hs = blockIdx.z;
    int t  = threadIdx.x;
    int j  = jc*128 + t;
    int h0 = hs*128;
    __shared__ float qs[32][128];
    #pragma unroll 8
    for (int r = 0; r < 32; r++) qs[r][t] = g_qbuf[r*HH + h0 + t];
    __syncthreads();
    float acc[32];
    #pragma unroll
    for (int b = 0; b < 32; b++) acc[b] = 0.f;
    for (int hh = 0; hh < 128; hh++) {
        float w = Wt_W[((size_t)k*HH + h0 + hh)*HH + j];
        #pragma unroll
        for (int b = 0; b < 32; b++) acc[b] = fmaf(qs[b][hh], w, acc[b]);
    }
    #pragma unroll
    for (int b = 0; b < 32; b++) atomicAdd(&g_Wht[(k*BB + b)*HH + j], acc[b]);
}

// ---------------- scores[k,b,s] = We . tanh(W_hs + W_ht) + We_b ----------------
__global__ __launch_bounds__(256)
void k_scores(const float* __restrict__ WeW, const float* __restrict__ Web) {
    int kb = blockIdx.x;
    int sc = blockIdx.y;
    int k = kb / BB;
    __shared__ float4 shW[HH/4];
    __shared__ float4 shE[HH/4];
    if (threadIdx.x < HH/4) {
        shW[threadIdx.x] = ((const float4*)(g_Wht + (size_t)kb*HH))[threadIdx.x];
        shE[threadIdx.x] = ((const float4*)(WeW + (size_t)k*HH))[threadIdx.x];
    }
    __syncthreads();
    int warp = threadIdx.x >> 5, lane = threadIdx.x & 31;
    float web = Web[k];
    for (int s = sc*128 + warp; s < sc*128 + 128; s += 8) {
        const float4* row = (const float4*)(g_Whs + ((size_t)kb*SS + s)*HH);
        float sum = 0.f;
        #pragma unroll
        for (int i = 0; i < 6; i++) {
            int idx = lane + i*32;
            float4 v = row[idx];
            float4 w = shW[idx];
            float4 e = shE[idx];
            float x0 = v.x + w.x, x1 = v.y + w.y, x2 = v.z + w.z, x3 = v.w + w.w;
            float t0 = 1.f - __fdividef(2.f, __expf(2.f*x0) + 1.f);
            float t1 = 1.f - __fdividef(2.f, __expf(2.f*x1) + 1.f);
            float t2 = 1.f - __fdividef(2.f, __expf(2.f*x2) + 1.f);
            float t3 = 1.f - __fdividef(2.f, __expf(2.f*x3) + 1.f);
            sum = fmaf(t0, e.x, sum);
            sum = fmaf(t1, e.y, sum);
            sum = fmaf(t2, e.z, sum);
            sum = fmaf(t3, e.w, sum);
        }
        #pragma unroll
        for (int o = 16; o; o >>= 1) sum += __shfl_xor_sync(0xffffffffu, sum, o);
        if (lane == 0) g_scores[kb*SS + s] = sum + web;
    }
}

// ---------------- softmax over S, in place ----------------
__global__ void k_softmax() {
    __shared__ float red[256];
    int row = blockIdx.x;
    float* p = g_scores + (size_t)row * SS;
    int t = threadIdx.x;
    float a = p[t], b = p[t + 256];
    red[t] = fmaxf(a, b);
    __syncthreads();
    for (int o = 128; o; o >>= 1) { if (t < o) red[t] = fmaxf(red[t], red[t+o]); __syncthreads(); }
    float m = red[0];
    __syncthreads();
    float e0 = __expf(a - m), e1 = __expf(b - m);
    red[t] = e0 + e1;
    __syncthreads();
    for (int o = 128; o; o >>= 1) { if (t < o) red[t] += red[t+o]; __syncthreads(); }
    float inv = 1.f / red[0];
    p[t] = e0 * inv;
    p[t + 256] = e1 * inv;
}

// ---------------- alpha_linear, prob (hop 0), argmax ----------------
__global__ void k_alpha(const float* __restrict__ hw, const float* __restrict__ hb,
                        float* __restrict__ out_prob, int hop) {
    int b = blockIdx.x;
    int s = threadIdx.x;
    float al = hb[0];
    #pragma unroll
    for (int k = 0; k < KK; k++) al = fmaf(g_scores[(k*BB + b)*SS + s], hw[k], al);
    __shared__ float ssq[512];
    __shared__ float sval[512];
    __shared__ int   sidx[512];
    ssq[s] = al * al; sval[s] = al; sidx[s] = s;
    __syncthreads();
    for (int o = 256; o; o >>= 1) {
        if (s < o) {
            ssq[s] += ssq[s + o];
            float v2 = sval[s + o]; int i2 = sidx[s + o];
            if (v2 > sval[s] || (v2 == sval[s] && i2 < sidx[s])) { sval[s] = v2; sidx[s] = i2; }
        }
        __syncthreads();
    }
    if (s == 0) g_idx[b] = sidx[0];
    if (hop == 0) out_prob[b*SS + s] = al / sqrtf(ssq[0]);
}

// ---------------- GRU ----------------
__global__ void k_gru_init(const float* __restrict__ bih, const float* __restrict__ bhh) {
    int t = blockIdx.x * 256 + threadIdx.x;
    if (t < BB*H3) { int j = t % H3; g_GX[t] = bih[j]; g_GH[t] = bhh[j]; }
}

__global__ void k_grugemm(const float* __restrict__ Wih, const float* __restrict__ Whh,
                          const float* __restrict__ text) {
    int jc = blockIdx.x;
    int ks = blockIdx.y;
    int bg = blockIdx.z;
    int t = threadIdx.x;
    int j = jc*256 + t;
    int i0 = ks*256;
    __shared__ float xs[8][256];
    int i = i0 + t;
    #pragma unroll
    for (int r = 0; r < 8; r++) {
        int b = bg*8 + r;
        float v;
        if (i < 768)       v = g_qbuf[b*HH + i];
        else if (i < 1536) v = text[((size_t)b*SS + g_idx[b])*HH + (i - 768)];
        else               v = g_hbuf[b*HH + (i - 1536)];
        xs[r][t] = v;
    }
    __syncthreads();
    const float* W; int wi0; float* G;
    if (i0 < 1536) { W = Wih; wi0 = i0;        G = g_GX; }
    else           { W = Whh; wi0 = i0 - 1536; G = g_GH; }
    float acc[8];
    #pragma unroll
    for (int r = 0; r < 8; r++) acc[r] = 0.f;
    #pragma unroll 4
    for (int kk = 0; kk < 256; kk++) {
        float w = W[(size_t)(wi0 + kk)*H3 + j];
        #pragma unroll
        for (int r = 0; r < 8; r++) acc[r] = fmaf(xs[r][kk], w, acc[r]);
    }
    #pragma unroll
    for (int r = 0; r < 8; r++) atomicAdd(&G[(bg*8 + r)*H3 + j], acc[r]);
}

__global__ void k_grugate(float* __restrict__ out_h, int hop) {
    int t = blockIdx.x * 256 + threadIdx.x;
    if (t >= BB*HH) return;
    int b = t / HH, j = t % HH;
    float gxr = g_GX[b*H3 + j],        ghr = g_GH[b*H3 + j];
    float gxz = g_GX[b*H3 + HH + j],   ghz = g_GH[b*H3 + HH + j];
    float gxn = g_GX[b*H3 + 2*HH + j], ghn = g_GH[b*H3 + 2*HH + j];
    float r = 1.f / (1.f + expf(-(gxr + ghr)));
    float z = 1.f / (1.f + expf(-(gxz + ghz)));
    float n = tanhf(gxn + r * ghn);
    float hprev = g_hbuf[t];
    float hn = (1.f - z) * n + z * hprev;
    g_hbuf[t] = hn;
    g_qbuf[t] = hn;
    out_h[((size_t)b*HOPS + hop)*HH + j] = hn;
}

// ---------------- launch ----------------
extern "C" void kernel_launch(void* const* d_in, const int* in_sizes, int n_in,
                              void* d_out, int out_size) {
    const float* question = (const float*)d_in[0];
    const float* text     = (const float*)d_in[1];
    const float* pw_W     = (const float*)d_in[2];
    const float* pw_b     = (const float*)d_in[3];
    const float* Ws_W     = (const float*)d_in[4];
    const float* Ws_b     = (const float*)d_in[5];
    const float* Wt_W     = (const float*)d_in[6];
    const float* Wt_b     = (const float*)d_in[7];
    const float* We_W     = (const float*)d_in[8];
    const float* We_b     = (const float*)d_in[9];
    const float* headw_W  = (const float*)d_in[10];
    const float* headw_b  = (const float*)d_in[11];
    const float* gru_Wih  = (const float*)d_in[12];
    const float* gru_Whh  = (const float*)d_in[13];
    const float* gru_bih  = (const float*)d_in[14];
    const float* gru_bhh  = (const float*)d_in[15];

    float* out_prob = (float*)d_out;
    float* out_h    = (float*)d_out + BB*SS;

    float *p_Wc, *p_bc, *p_Whs;
    __nv_bfloat16 *p_tAhi, *p_tAlo, *p_pwhi, *p_pwlo, *p_WsThi, *p_WsTlo, *p_WcThi, *p_WcTlo;
    cudaGetSymbolAddress((void**)&p_Wc,    g_Wc);
    cudaGetSymbolAddress((void**)&p_bc,    g_bc);
    cudaGetSymbolAddress((void**)&p_Whs,   g_Whs);
    cudaGetSymbolAddress((void**)&p_tAhi,  g_tAhi);
    cudaGetSymbolAddress((void**)&p_tAlo,  g_tAlo);
    cudaGetSymbolAddress((void**)&p_pwhi,  g_pwhi);
    cudaGetSymbolAddress((void**)&p_pwlo,  g_pwlo);
    cudaGetSymbolAddress((void**)&p_WsThi, g_WsThi);
    cudaGetSymbolAddress((void**)&p_WsTlo, g_WsTlo);
    cudaGetSymbolAddress((void**)&p_WcThi, g_WcThi);
    cudaGetSymbolAddress((void**)&p_WcTlo, g_WcTlo);

    cudaFuncSetAttribute(k_hmma3, cudaFuncAttributeMaxDynamicSharedMemorySize, SMEM3);

    k_prologue<<<(BB*HH + 255)/256, 256>>>(question);
    k_bc<<<dim3(KK, HH/256), 256>>>(pw_b, Ws_W, Ws_b);

    // split conversions
    k_split<<<(MROWS*HH + 255)/256, 256>>>(text, p_tAhi, p_tAlo, MROWS*HH);
    k_split<<<(KK*HH*HH + 255)/256, 256>>>(pw_W, p_pwhi, p_pwlo, KK*HH*HH);
    k_splitT<<<dim3(HH/32, HH/32, KK), dim3(32, 8)>>>(Ws_W, p_WsThi, p_WsTlo);

    // Wc[k] = pw_W[k] @ Ws_W[k]  (HMMA split-bf16)
    k_hmma3<<<dim3(HH/128, HH/128, KK), 256, SMEM3>>>(
        p_pwhi, p_pwlo, (size_t)HH*HH,
        p_WsThi, p_WsTlo, (size_t)HH*HH,
        p_Wc, (size_t)HH*HH, nullptr, HH);

    k_splitT<<<dim3(HH/32, HH/32, KK), dim3(32, 8)>>>(p_Wc, p_WcThi, p_WcTlo);

    // W_hs[k] = text @ Wc[k] + bc[k]  (HMMA split-bf16)
    k_hmma3<<<dim3(HH/128, MROWS/128, KK), 256, SMEM3>>>(
        p_tAhi, p_tAlo, 0,
        p_WcThi, p_WcTlo, (size_t)HH*HH,
        p_Whs, (size_t)MROWS*HH, p_bc, HH);

    for (int hop = 0; hop < HOPS; hop++) {
        k_init_wht<<<(KK*BB*HH + 255)/256, 256>>>(Wt_b);
        k_wht<<<dim3(KK, HH/128, HH/128), 128>>>(Wt_W);
        k_scores<<<dim3(KK*BB, SS/128), 256>>>(We_W, We_b);
        k_softmax<<<KK*BB, 256>>>();
        k_alpha<<<BB, 512>>>(headw_W, headw_b, out_prob, hop);
        k_gru_init<<<(BB*H3 + 255)/256, 256>>>(gru_bih, gru_bhh);
        k_grugemm<<<dim3(H3/256, H3/256, BB/8), 256>>>(gru_Wih, gru_Whh, text);
        k_grugate<<<(BB*HH + 255)/256, 256>>>(out_h, hop);
    }
}